// round 15
// baseline (speedup 1.0000x reference)
#include <cuda_runtime.h>
#include <cuda_fp16.h>
#include <cstdint>

#define N_NODES 50000
#define N_EDGES 800000
#define EDGE_CAP (N_EDGES + 8 * N_NODES)   // padded CSR capacity
#define DIM 128
#define DIM4 32
#define AS 132      // A smem stride (floats)
#define WS 136      // W smem stride (floats)
#define TM 128      // gemm tile rows
#define GEMM_T 512  // gemm threads
#define CSR_B 512   // k_csr block size
#define CSR_G 148   // k_csr grid (must be <= SM count: all blocks co-resident)

// Scratch (allocation-free: __device__ globals)
__device__ __half g_h[N_NODES * DIM];   // layer-1 gemm out (fp16 gather src)
__device__ float  g_z[N_NODES * DIM];   // layer-1 activations (fp32, gemm2 in)
__device__ __half g_h2[N_NODES * DIM];  // layer-2 gemm out (fp16 gather src)
__device__ unsigned long long g_pack[N_NODES];  // (cnt<<32) | fixpt weight sum
__device__ float g_dinv[N_NODES];
__device__ int   g_cursor[N_NODES];
__device__ int   g_rowstart[N_NODES + 1];
__device__ int   g_blocksums[CSR_G];
__device__ int2  g_edges[EDGE_CAP];     // {src, half2(norm,norm) bits}, rows padded to 8

// global barrier state (zero-init; g_release monotonic across graph replays)
__device__ unsigned g_arrive[4];
__device__ volatile unsigned g_release;

// ---------------------------------------------------------------------------
// fused CSR build: zero -> count -> scan(+dinv) -> offsets -> reorder+pad
// Persistent 148-block kernel with software global barriers.
// ---------------------------------------------------------------------------
__device__ __forceinline__ void gbar(unsigned target) {
    __syncthreads();
    if (threadIdx.x == 0) {
        __threadfence();
        unsigned old = atomicAdd(&g_arrive[target & 3u], 1u);
        if (old == gridDim.x - 1) {
            g_arrive[target & 3u] = 0u;
            __threadfence();
            g_release = target;
        } else {
            while (g_release < target) { }
        }
    }
    __syncthreads();
    __threadfence();
}

__device__ __forceinline__ int warp_incl_scan(int x, int lane) {
    #pragma unroll
    for (int o = 1; o < 32; o <<= 1) {
        int y = __shfl_up_sync(0xffffffffu, x, o);
        if (lane >= o) x += y;
    }
    return x;
}

__global__ void __launch_bounds__(CSR_B, 1)
k_csr(const int* __restrict__ src, const int* __restrict__ dst,
      const float* __restrict__ ew, int n, int e) {
    __shared__ int warpsums[16];
    __shared__ int sh_bc;
    __shared__ unsigned sh_base;

    const int tid  = threadIdx.x;
    const int lane = tid & 31;
    const int warp = tid >> 5;
    const int bid  = blockIdx.x;
    const int gsz  = gridDim.x * blockDim.x;
    const int gtid = bid * blockDim.x + tid;

    if (tid == 0) sh_base = g_release;   // stable: no block can release before we arrive
    __syncthreads();
    const unsigned base = sh_base;

    // P0: zero pack + cursor
    for (int i = gtid; i < n; i += gsz) { g_pack[i] = 0ull; g_cursor[i] = 0; }
    gbar(base + 1);

    // P1: packed count + weighted degree
    for (int i = gtid; i < e; i += gsz) {
        int d = dst[i];
        unsigned fx = __float2uint_rn(ew[i] * 16777216.0f);
        atomicAdd(&g_pack[d], (1ull << 32) | (unsigned long long)fx);
    }
    gbar(base + 2);

    // P2: per-block scan of PADDED counts over node chunk [bid*chunk, ...), + dinv
    const int chunk = (n + CSR_G - 1) / CSR_G;   // 338
    const int nb0 = bid * chunk;
    const int nb = min(chunk, n - nb0);          // >0 for all blocks (148*338>=n)
    int carry = 0;
    for (int i0 = 0; i0 < nb; i0 += CSR_B) {
        int i = nb0 + i0 + tid;
        int v = 0;
        if (i0 + tid < nb) {
            unsigned long long p = g_pack[i];
            int cnt = (int)(p >> 32);
            v = (cnt + 7) & ~7;                  // padded count
            float deg = 1.0f + (float)(unsigned)(p & 0xffffffffu) * (1.0f / 16777216.0f);
            g_dinv[i] = rsqrtf(deg);
        }
        int x = warp_incl_scan(v, lane);
        if (lane == 31) warpsums[warp] = x;
        __syncthreads();
        if (tid < 32) {
            int s = (tid < 16) ? warpsums[tid] : 0;
            int xs = warp_incl_scan(s, tid);
            if (tid < 16) warpsums[tid] = xs - s;
        }
        __syncthreads();
        int excl = (x - v) + warpsums[warp];
        if (i0 + tid < nb) g_rowstart[i] = carry + excl;
        __syncthreads();
        if (tid == CSR_B - 1 || i0 + tid == nb - 1) {
            if (i0 + tid == min(i0 + CSR_B, nb) - 1) sh_bc = carry + excl + v;
        }
        __syncthreads();
        carry = sh_bc;
    }
    if (tid == 0) g_blocksums[bid] = carry;
    gbar(base + 3);

    // P3: add exclusive block offset; last block writes rowstart[n]
    {
        int sum = 0;
        if (tid < 32) {
            for (int c = tid; c < bid; c += 32) sum += g_blocksums[c];
            #pragma unroll
            for (int o = 16; o; o >>= 1) sum += __shfl_down_sync(0xffffffffu, sum, o);
            if (tid == 0) sh_bc = sum;
        }
        __syncthreads();
        int offset = sh_bc;
        for (int i0 = tid; i0 < nb; i0 += CSR_B) g_rowstart[nb0 + i0] += offset;
        if (bid == CSR_G - 1 && tid == 0) g_rowstart[n] = offset + carry;
    }
    gbar(base + 4);

    // P4: reorder real edges + fill padding (disjoint slots, no barrier needed)
    for (int i = gtid; i < e; i += gsz) {
        int s = src[i];
        int d = dst[i];
        float nrm = g_dinv[s] * ew[i] * g_dinv[d];
        __half2 h2 = __half2half2(__float2half_rn(nrm));
        int p = g_rowstart[d] + atomicAdd(&g_cursor[d], 1);
        g_edges[p] = make_int2(s, *(int*)&h2);
    }
    for (int i = gtid; i < n; i += gsz) {
        int cnt = (int)(g_pack[i] >> 32);
        int start = g_rowstart[i];
        int pend = start + ((cnt + 7) & ~7);
        for (int j = start + cnt; j < pend; j++)
            g_edges[j] = make_int2(i, 0);        // half2(0,0) bits == 0
    }
}

// ---------------------------------------------------------------------------
// tf32 tensor GEMM (v3): 512 thr / 16 warps (8m x 2n), warp tile 16x64.
// Persistent, cp.async double-buffered A, 128x128 block tile. fp16 epilogue.
// ---------------------------------------------------------------------------
__device__ __forceinline__ uint32_t f2tf32(float v) {
    uint32_t o;
    asm("cvt.rna.tf32.f32 %0, %1;" : "=r"(o) : "f"(v));
    return o;
}

__device__ __forceinline__ void mma_tf32(float* c, const uint32_t* a,
                                         uint32_t b0, uint32_t b1) {
    asm volatile(
        "mma.sync.aligned.m16n8k8.row.col.f32.tf32.tf32.f32 "
        "{%0,%1,%2,%3}, {%4,%5,%6,%7}, {%8,%9}, {%0,%1,%2,%3};"
        : "+f"(c[0]), "+f"(c[1]), "+f"(c[2]), "+f"(c[3])
        : "r"(a[0]), "r"(a[1]), "r"(a[2]), "r"(a[3]), "r"(b0), "r"(b1));
}

__device__ __forceinline__ void load_tileA(float* dst, const float* __restrict__ in,
                                           int t, int n, int tid) {
    int row0 = t * TM;
    #pragma unroll 2
    for (int i = tid; i < TM * 32; i += GEMM_T) {
        int r = i >> 5, c = (i & 31) << 2;
        float* d = dst + r * AS + c;
        if (row0 + r < n) {
            uint32_t s = (uint32_t)__cvta_generic_to_shared(d);
            asm volatile("cp.async.cg.shared.global [%0], [%1], 16;"
                         :: "r"(s), "l"(in + (size_t)(row0 + r) * DIM + c));
        } else {
            *(float4*)d = make_float4(0.f, 0.f, 0.f, 0.f);
        }
    }
}

__global__ void __launch_bounds__(GEMM_T, 1)
k_gemm(const float* __restrict__ in, const float* __restrict__ W,
       __half* __restrict__ out, int n) {
    extern __shared__ uint32_t smem[];
    uint32_t* Ws = smem;                                  // [128][WS] tf32
    float* As0 = (float*)(smem + DIM * WS);               // [128][AS] fp32
    float* As1 = As0 + TM * AS;

    const int tid  = threadIdx.x;
    const int lane = tid & 31;
    const int warp = tid >> 5;
    const int warp_m = (warp & 7) * 16;
    const int warp_n = (warp >> 3) * 64;
    const int ntiles = (n + TM - 1) / TM;

    for (int i = tid; i < DIM * DIM4; i += GEMM_T) {
        int k = i >> 5, c4 = (i & 31) << 2;
        float4 v = ((const float4*)W)[i];
        uint32_t* p = Ws + k * WS + c4;
        p[0] = f2tf32(v.x); p[1] = f2tf32(v.y); p[2] = f2tf32(v.z); p[3] = f2tf32(v.w);
    }

    int t = blockIdx.x;
    if (t < ntiles) {
        load_tileA(As0, in, t, n, tid);
        asm volatile("cp.async.commit_group;");
    }

    int buf = 0;
    const int ar  = lane >> 2;
    const int akc = lane & 3;

    for (; t < ntiles; t += gridDim.x) {
        int tn = t + gridDim.x;
        if (tn < ntiles) {
            load_tileA(buf ? As0 : As1, in, tn, n, tid);
            asm volatile("cp.async.commit_group;");
            asm volatile("cp.async.wait_group 1;");
        } else {
            asm volatile("cp.async.wait_group 0;");
        }
        __syncthreads();

        const float* A = buf ? As1 : As0;
        float acc[8][4];
        #pragma unroll
        for (int nt = 0; nt < 8; nt++)
            #pragma unroll
            for (int q = 0; q < 4; q++) acc[nt][q] = 0.0f;

        #pragma unroll
        for (int ks = 0; ks < 16; ks++) {
            const int k0 = ks * 8;
            uint32_t a[4];
            {
                int r = warp_m + ar;
                a[0] = f2tf32(A[r * AS + k0 + akc]);
                a[1] = f2tf32(A[(r + 8) * AS + k0 + akc]);
                a[2] = f2tf32(A[r * AS + k0 + akc + 4]);
                a[3] = f2tf32(A[(r + 8) * AS + k0 + akc + 4]);
            }
            #pragma unroll
            for (int nt = 0; nt < 8; nt++) {
                int bn = warp_n + nt * 8 + (lane >> 2);
                int bk = k0 + (lane & 3);
                uint32_t b0 = Ws[bk * WS + bn];
                uint32_t b1 = Ws[(bk + 4) * WS + bn];
                mma_tf32(acc[nt], a, b0, b1);
            }
        }

        int row0 = t * TM;
        int rbase = row0 + warp_m + (lane >> 2);
        #pragma unroll
        for (int nt = 0; nt < 8; nt++) {
            int col = warp_n + nt * 8 + 2 * (lane & 3);
            __half2 p0, p1;
            p0.x = __float2half_rn(acc[nt][0]);
            p0.y = __float2half_rn(acc[nt][1]);
            p1.x = __float2half_rn(acc[nt][2]);
            p1.y = __float2half_rn(acc[nt][3]);
            if (rbase < n)
                *(__half2*)(out + (size_t)rbase * DIM + col) = p0;
            if (rbase + 8 < n)
                *(__half2*)(out + (size_t)(rbase + 8) * DIM + col) = p1;
        }
        __syncthreads();
        buf ^= 1;
    }
}

// ---------------------------------------------------------------------------
// Gather-aggregate v5: fp16 gather + HFMA2, rows padded to 8 (no tail loop).
// ---------------------------------------------------------------------------
__global__ void k_agg(const __half* __restrict__ h, const float* __restrict__ b,
                      float* __restrict__ out, int node0, int node1) {
    int t = blockIdx.x * blockDim.x + threadIdx.x;
    int node = node0 + (t >> 5);
    int lane = t & 31;
    if (node >= node1) return;

    int beg = g_rowstart[node];
    int end = g_rowstart[node + 1];

    float di = g_dinv[node];
    float sl = di * di;
    uint2 hs = *(const uint2*)(h + (size_t)node * DIM + lane * 4);
    float2 h0 = __half22float2(*(__half2*)&hs.x);
    float2 h1 = __half22float2(*(__half2*)&hs.y);
    float4 acc = make_float4(h0.x * sl, h0.y * sl, h1.x * sl, h1.y * sl);

    const __half2 hz = __half2half2(__ushort_as_half(0));

    for (int j = beg; j < end; j += 8) {   // end-beg always multiple of 8
        int2 ed[8];
        #pragma unroll
        for (int q = 0; q < 8; q++) ed[q] = g_edges[j + q];
        uint2 v[8];
        #pragma unroll
        for (int q = 0; q < 8; q++)
            v[q] = *(const uint2*)(h + (size_t)ed[q].x * DIM + lane * 4);
        #pragma unroll
        for (int g = 0; g < 2; g++) {
            __half2 a0 = hz, a1 = hz;
            #pragma unroll
            for (int q = g * 4; q < g * 4 + 4; q++) {
                __half2 nr2 = *(__half2*)&ed[q].y;
                a0 = __hfma2(nr2, *(__half2*)&v[q].x, a0);
                a1 = __hfma2(nr2, *(__half2*)&v[q].y, a1);
            }
            float2 f0 = __half22float2(a0);
            float2 f1 = __half22float2(a1);
            acc.x += f0.x; acc.y += f0.y; acc.z += f1.x; acc.w += f1.y;
        }
    }

    float4 bv = ((const float4*)b)[lane];
    float4 o;
    o.x = fmaxf(acc.x + bv.x, 0.0f);
    o.y = fmaxf(acc.y + bv.y, 0.0f);
    o.z = fmaxf(acc.z + bv.z, 0.0f);
    o.w = fmaxf(acc.w + bv.w, 0.0f);
    ((float4*)(out + (size_t)node * DIM))[lane] = o;
}

// ---------------------------------------------------------------------------
extern "C" void kernel_launch(void* const* d_in, const int* in_sizes, int n_in,
                              void* d_out, int out_size) {
    const float* x   = (const float*)d_in[0];
    const int*   ei  = (const int*)d_in[1];
    const float* ew  = (const float*)d_in[2];
    const float* W1  = (const float*)d_in[3];
    const float* b1  = (const float*)d_in[4];
    const float* W2  = (const float*)d_in[5];
    const float* b2  = (const float*)d_in[6];
    float* out = (float*)d_out;

    const int n = in_sizes[0] / DIM;
    const int e = in_sizes[2];
    const int* src = ei;
    const int* dst = ei + e;

    const int T = 256;

    static cudaStream_t s2 = nullptr;
    static cudaEvent_t ev_fork = nullptr, ev_join = nullptr, ev_g2 = nullptr;
    static cudaEvent_t ev_c0 = nullptr, ev_c1 = nullptr;
    static bool init_done = false;
    const int GEMM_SMEM = (DIM * WS + 2 * TM * AS) * sizeof(uint32_t);  // 200KB
    if (!init_done) {
        cudaFuncSetAttribute(k_gemm, cudaFuncAttributeMaxDynamicSharedMemorySize, GEMM_SMEM);
        cudaStreamCreateWithFlags(&s2, cudaStreamNonBlocking);
        cudaEventCreateWithFlags(&ev_fork, cudaEventDisableTiming);
        cudaEventCreateWithFlags(&ev_join, cudaEventDisableTiming);
        cudaEventCreateWithFlags(&ev_g2, cudaEventDisableTiming);
        cudaEventCreateWithFlags(&ev_c0, cudaEventDisableTiming);
        cudaEventCreateWithFlags(&ev_c1, cudaEventDisableTiming);
        init_done = true;
    }
    const int GEMM_GRID = 148;

    __half* g_h_p;   cudaGetSymbolAddress((void**)&g_h_p, g_h);
    float*  g_z_p;   cudaGetSymbolAddress((void**)&g_z_p, g_z);
    __half* g_h2_p;  cudaGetSymbolAddress((void**)&g_h2_p, g_h2);

    // fork: fused CSR (1 kernel) on s2, gemm1 halves on main.
    cudaEventRecord(ev_fork, 0);
    cudaStreamWaitEvent(s2, ev_fork, 0);

    const int gh = (n + 1) / 2;
    k_csr<<<CSR_G, CSR_B, 0, s2>>>(src, dst, ew, n, e);                 // 0
    cudaEventRecord(ev_join, s2);
    k_gemm<<<GEMM_GRID, GEMM_T, GEMM_SMEM>>>(x, W1, g_h_p, gh);         // 1
    k_gemm<<<GEMM_GRID, GEMM_T, GEMM_SMEM>>>(
        x + (size_t)gh * DIM, W1, g_h_p + (size_t)gh * DIM, n - gh);    // 2
    cudaStreamWaitEvent(0, ev_join, 0);

    // 2-chunk agg1 || gemm2 overlap. gemm2 writes g_h2.
    const int half = (n + 1) / 2;
    {
        int gWc = (half * 32 + T - 1) / T;
        k_agg<<<gWc, T>>>(g_h_p, b1, g_z_p, 0, half);                   // 3 <- PROFILED
        cudaEventRecord(ev_c0, 0);
        cudaStreamWaitEvent(s2, ev_c0, 0);
        k_gemm<<<GEMM_GRID, GEMM_T, GEMM_SMEM, s2>>>(g_z_p, W2, g_h2_p, half);  // 4

        int nodes1 = n - half;
        int gWc1 = (nodes1 * 32 + T - 1) / T;
        k_agg<<<gWc1, T>>>(g_h_p, b1, g_z_p, half, n);                  // 5
        cudaEventRecord(ev_c1, 0);
        cudaStreamWaitEvent(s2, ev_c1, 0);
        k_gemm<<<GEMM_GRID, GEMM_T, GEMM_SMEM, s2>>>(
            g_z_p + (size_t)half * DIM, W2, g_h2_p + (size_t)half * DIM, nodes1);  // 6
    }
    cudaEventRecord(ev_g2, s2);
    cudaStreamWaitEvent(0, ev_g2, 0);

    // layer 2 agg (full range), gathers from g_h2
    int gW = (n * 32 + T - 1) / T;
    k_agg<<<gW, T>>>(g_h2_p, b2, out, 0, n);                            // 7
}

// round 17
// speedup vs baseline: 1.0566x; 1.0566x over previous
#include <cuda_runtime.h>
#include <cuda_fp16.h>
#include <cstdint>

#define N_NODES 50000
#define N_EDGES 800000
#define EDGE_CAP (N_EDGES + 8 * N_NODES)   // padded CSR capacity
#define DIM 128
#define DIM4 32
#define AS 132      // A smem stride (floats)
#define WS 136      // W smem stride (floats)
#define TM 128      // gemm tile rows
#define GEMM_T 512  // gemm threads
#define SCAN_B 256  // scan block size

// Scratch (allocation-free: __device__ globals)
__device__ __half g_h[N_NODES * DIM];   // layer-1 gemm out (fp16 gather src)
__device__ float  g_z[N_NODES * DIM];   // layer-1 activations (fp32, gemm2 in)
__device__ __half g_h2[N_NODES * DIM];  // layer-2 gemm out (fp16 gather src)
__device__ unsigned long long g_pack[N_NODES];  // (cnt<<32) | fixpt weight sum
__device__ float g_dinv[N_NODES];
__device__ int   g_cursor[N_NODES];
__device__ int   g_rowstart[N_NODES + 1];
__device__ int   g_blocksums[256];
__device__ int2  g_edges[EDGE_CAP];     // {src, half2(norm,norm) bits}, rows padded to 8

// ---------------------------------------------------------------------------
__global__ void k_init(int n) {
    int i = blockIdx.x * blockDim.x + threadIdx.x;
    if (i < n) { g_pack[i] = 0ull; g_cursor[i] = 0; }
}

// packed histogram + weighted degree (one 64-bit atomic per edge)
__global__ void k_count(const int* __restrict__ dst, const float* __restrict__ ew, int e) {
    int i = blockIdx.x * blockDim.x + threadIdx.x;
    if (i < e) {
        int d = dst[i];
        unsigned fx = __float2uint_rn(ew[i] * 16777216.0f);
        atomicAdd(&g_pack[d], (1ull << 32) | (unsigned long long)fx);
    }
}

// ---------------------------------------------------------------------------
__device__ __forceinline__ int warp_incl_scan(int x, int lane) {
    #pragma unroll
    for (int o = 1; o < 32; o <<= 1) {
        int y = __shfl_up_sync(0xffffffffu, x, o);
        if (lane >= o) x += y;
    }
    return x;
}

// scan phase 1 over PADDED counts (+ fused dinv)
__global__ void k_scan1(int n) {
    __shared__ int warpsums[8];
    const int lane = threadIdx.x & 31;
    const int warp = threadIdx.x >> 5;
    int i = blockIdx.x * SCAN_B + threadIdx.x;
    int v = 0;
    if (i < n) {
        unsigned long long p = g_pack[i];
        int cnt = (int)(p >> 32);
        v = (cnt + 7) & ~7;   // pad row to multiple of 8
        float deg = 1.0f + (float)(unsigned)(p & 0xffffffffu) * (1.0f / 16777216.0f);
        g_dinv[i] = rsqrtf(deg);
    }
    int x = warp_incl_scan(v, lane);
    if (lane == 31) warpsums[warp] = x;
    __syncthreads();
    if (threadIdx.x < 32) {
        int s = (threadIdx.x < 8) ? warpsums[threadIdx.x] : 0;
        int xs = warp_incl_scan(s, threadIdx.x);
        if (threadIdx.x < 8) warpsums[threadIdx.x] = xs - s;
    }
    __syncthreads();
    int excl = (x - v) + warpsums[warp];
    if (i < n) g_rowstart[i] = excl;
    if (threadIdx.x == SCAN_B - 1) g_blocksums[blockIdx.x] = excl + v;
}

// scan phase 2+3 merged; also writes rowstart[n] = padded total
__global__ void k_scan3(int n) {
    __shared__ int off_s;
    if (threadIdx.x < 32) {
        int sum = 0;
        for (int c = (int)threadIdx.x; c < (int)blockIdx.x; c += 32)
            sum += g_blocksums[c];
        #pragma unroll
        for (int o = 16; o; o >>= 1) sum += __shfl_down_sync(0xffffffffu, sum, o);
        if (threadIdx.x == 0) off_s = sum;
    }
    __syncthreads();
    int i = blockIdx.x * SCAN_B + threadIdx.x;
    if (i < n) {
        int rs = g_rowstart[i] + off_s;
        g_rowstart[i] = rs;
        if (i == n - 1) {
            int cnt = (int)(g_pack[i] >> 32);
            g_rowstart[n] = rs + ((cnt + 7) & ~7);
        }
    }
}

__global__ void k_reorder(const int* __restrict__ src, const int* __restrict__ dst,
                          const float* __restrict__ ew, int e) {
    int i = blockIdx.x * blockDim.x + threadIdx.x;
    if (i < e) {
        int s = src[i];
        int d = dst[i];
        float nrm = g_dinv[s] * ew[i] * g_dinv[d];
        __half2 h2 = __half2half2(__float2half_rn(nrm));
        int p = g_rowstart[d] + atomicAdd(&g_cursor[d], 1);
        g_edges[p] = make_int2(s, *(int*)&h2);
    }
}

// fill pad slots with (src=node, norm=0) — disjoint from reorder's slots
__global__ void k_pad(int n) {
    int i = blockIdx.x * blockDim.x + threadIdx.x;
    if (i < n) {
        int cnt = (int)(g_pack[i] >> 32);
        int start = g_rowstart[i];
        int pend = start + ((cnt + 7) & ~7);
        for (int j = start + cnt; j < pend; j++)
            g_edges[j] = make_int2(i, 0);
    }
}

// ---------------------------------------------------------------------------
// tf32 tensor GEMM (v3): 512 thr / 16 warps (8m x 2n), warp tile 16x64.
// Persistent, cp.async double-buffered A, 128x128 block tile. fp16 epilogue.
// ---------------------------------------------------------------------------
__device__ __forceinline__ uint32_t f2tf32(float v) {
    uint32_t o;
    asm("cvt.rna.tf32.f32 %0, %1;" : "=r"(o) : "f"(v));
    return o;
}

__device__ __forceinline__ void mma_tf32(float* c, const uint32_t* a,
                                         uint32_t b0, uint32_t b1) {
    asm volatile(
        "mma.sync.aligned.m16n8k8.row.col.f32.tf32.tf32.f32 "
        "{%0,%1,%2,%3}, {%4,%5,%6,%7}, {%8,%9}, {%0,%1,%2,%3};"
        : "+f"(c[0]), "+f"(c[1]), "+f"(c[2]), "+f"(c[3])
        : "r"(a[0]), "r"(a[1]), "r"(a[2]), "r"(a[3]), "r"(b0), "r"(b1));
}

__device__ __forceinline__ void load_tileA(float* dst, const float* __restrict__ in,
                                           int t, int n, int tid) {
    int row0 = t * TM;
    #pragma unroll 2
    for (int i = tid; i < TM * 32; i += GEMM_T) {
        int r = i >> 5, c = (i & 31) << 2;
        float* d = dst + r * AS + c;
        if (row0 + r < n) {
            uint32_t s = (uint32_t)__cvta_generic_to_shared(d);
            asm volatile("cp.async.cg.shared.global [%0], [%1], 16;"
                         :: "r"(s), "l"(in + (size_t)(row0 + r) * DIM + c));
        } else {
            *(float4*)d = make_float4(0.f, 0.f, 0.f, 0.f);
        }
    }
}

__global__ void __launch_bounds__(GEMM_T, 1)
k_gemm(const float* __restrict__ in, const float* __restrict__ W,
       __half* __restrict__ out, int n) {
    extern __shared__ uint32_t smem[];
    uint32_t* Ws = smem;                                  // [128][WS] tf32
    float* As0 = (float*)(smem + DIM * WS);               // [128][AS] fp32
    float* As1 = As0 + TM * AS;

    const int tid  = threadIdx.x;
    const int lane = tid & 31;
    const int warp = tid >> 5;
    const int warp_m = (warp & 7) * 16;
    const int warp_n = (warp >> 3) * 64;
    const int ntiles = (n + TM - 1) / TM;

    for (int i = tid; i < DIM * DIM4; i += GEMM_T) {
        int k = i >> 5, c4 = (i & 31) << 2;
        float4 v = ((const float4*)W)[i];
        uint32_t* p = Ws + k * WS + c4;
        p[0] = f2tf32(v.x); p[1] = f2tf32(v.y); p[2] = f2tf32(v.z); p[3] = f2tf32(v.w);
    }

    int t = blockIdx.x;
    if (t < ntiles) {
        load_tileA(As0, in, t, n, tid);
        asm volatile("cp.async.commit_group;");
    }

    int buf = 0;
    const int ar  = lane >> 2;
    const int akc = lane & 3;

    for (; t < ntiles; t += gridDim.x) {
        int tn = t + gridDim.x;
        if (tn < ntiles) {
            load_tileA(buf ? As0 : As1, in, tn, n, tid);
            asm volatile("cp.async.commit_group;");
            asm volatile("cp.async.wait_group 1;");
        } else {
            asm volatile("cp.async.wait_group 0;");
        }
        __syncthreads();

        const float* A = buf ? As1 : As0;
        float acc[8][4];
        #pragma unroll
        for (int nt = 0; nt < 8; nt++)
            #pragma unroll
            for (int q = 0; q < 4; q++) acc[nt][q] = 0.0f;

        #pragma unroll
        for (int ks = 0; ks < 16; ks++) {
            const int k0 = ks * 8;
            uint32_t a[4];
            {
                int r = warp_m + ar;
                a[0] = f2tf32(A[r * AS + k0 + akc]);
                a[1] = f2tf32(A[(r + 8) * AS + k0 + akc]);
                a[2] = f2tf32(A[r * AS + k0 + akc + 4]);
                a[3] = f2tf32(A[(r + 8) * AS + k0 + akc + 4]);
            }
            #pragma unroll
            for (int nt = 0; nt < 8; nt++) {
                int bn = warp_n + nt * 8 + (lane >> 2);
                int bk = k0 + (lane & 3);
                uint32_t b0 = Ws[bk * WS + bn];
                uint32_t b1 = Ws[(bk + 4) * WS + bn];
                mma_tf32(acc[nt], a, b0, b1);
            }
        }

        int row0 = t * TM;
        int rbase = row0 + warp_m + (lane >> 2);
        #pragma unroll
        for (int nt = 0; nt < 8; nt++) {
            int col = warp_n + nt * 8 + 2 * (lane & 3);
            __half2 p0, p1;
            p0.x = __float2half_rn(acc[nt][0]);
            p0.y = __float2half_rn(acc[nt][1]);
            p1.x = __float2half_rn(acc[nt][2]);
            p1.y = __float2half_rn(acc[nt][3]);
            if (rbase < n)
                *(__half2*)(out + (size_t)rbase * DIM + col) = p0;
            if (rbase + 8 < n)
                *(__half2*)(out + (size_t)(rbase + 8) * DIM + col) = p1;
        }
        __syncthreads();
        buf ^= 1;
    }
}

// ---------------------------------------------------------------------------
// Gather-aggregate v6: fp16 gather + HFMA2, padded rows (no tail),
// edge metadata loaded as 4x LDG.128 per 8 edges (rows are 64B aligned).
// ---------------------------------------------------------------------------
__global__ void k_agg(const __half* __restrict__ h, const float* __restrict__ b,
                      float* __restrict__ out, int node0, int node1) {
    int t = blockIdx.x * blockDim.x + threadIdx.x;
    int node = node0 + (t >> 5);
    int lane = t & 31;
    if (node >= node1) return;

    int beg = g_rowstart[node];
    int end = g_rowstart[node + 1];

    float di = g_dinv[node];
    float sl = di * di;
    uint2 hs = *(const uint2*)(h + (size_t)node * DIM + lane * 4);
    float2 h0 = __half22float2(*(__half2*)&hs.x);
    float2 h1 = __half22float2(*(__half2*)&hs.y);
    float4 acc = make_float4(h0.x * sl, h0.y * sl, h1.x * sl, h1.y * sl);

    const __half2 hz = __half2half2(__ushort_as_half(0));

    for (int j = beg; j < end; j += 8) {   // row length is a multiple of 8
        // 8 edges = 64B = 4 int4 (j is a multiple of 8 -> 64B aligned)
        int4 e4[4];
        #pragma unroll
        for (int q = 0; q < 4; q++) e4[q] = ((const int4*)(g_edges + j))[q];
        uint2 v[8];
        #pragma unroll
        for (int q = 0; q < 4; q++) {
            v[2 * q]     = *(const uint2*)(h + (size_t)e4[q].x * DIM + lane * 4);
            v[2 * q + 1] = *(const uint2*)(h + (size_t)e4[q].z * DIM + lane * 4);
        }
        #pragma unroll
        for (int g = 0; g < 2; g++) {
            __half2 a0 = hz, a1 = hz;
            #pragma unroll
            for (int p = 0; p < 2; p++) {
                int qq = g * 2 + p;             // int4 index
                __half2 n0 = *(__half2*)&e4[qq].y;
                __half2 n1 = *(__half2*)&e4[qq].w;
                a0 = __hfma2(n0, *(__half2*)&v[2 * qq].x, a0);
                a1 = __hfma2(n0, *(__half2*)&v[2 * qq].y, a1);
                a0 = __hfma2(n1, *(__half2*)&v[2 * qq + 1].x, a0);
                a1 = __hfma2(n1, *(__half2*)&v[2 * qq + 1].y, a1);
            }
            float2 f0 = __half22float2(a0);
            float2 f1 = __half22float2(a1);
            acc.x += f0.x; acc.y += f0.y; acc.z += f1.x; acc.w += f1.y;
        }
    }

    float4 bv = ((const float4*)b)[lane];
    float4 o;
    o.x = fmaxf(acc.x + bv.x, 0.0f);
    o.y = fmaxf(acc.y + bv.y, 0.0f);
    o.z = fmaxf(acc.z + bv.z, 0.0f);
    o.w = fmaxf(acc.w + bv.w, 0.0f);
    ((float4*)(out + (size_t)node * DIM))[lane] = o;
}

// ---------------------------------------------------------------------------
extern "C" void kernel_launch(void* const* d_in, const int* in_sizes, int n_in,
                              void* d_out, int out_size) {
    const float* x   = (const float*)d_in[0];
    const int*   ei  = (const int*)d_in[1];
    const float* ew  = (const float*)d_in[2];
    const float* W1  = (const float*)d_in[3];
    const float* b1  = (const float*)d_in[4];
    const float* W2  = (const float*)d_in[5];
    const float* b2  = (const float*)d_in[6];
    float* out = (float*)d_out;

    const int n = in_sizes[0] / DIM;
    const int e = in_sizes[2];
    const int* src = ei;
    const int* dst = ei + e;

    const int T = 256;
    const int gN = (n + T - 1) / T;
    const int gE = (e + T - 1) / T;
    const int nScanBlk = (n + SCAN_B - 1) / SCAN_B;

    static cudaStream_t s2 = nullptr;
    static cudaEvent_t ev_fork = nullptr, ev_join = nullptr, ev_g2 = nullptr;
    static cudaEvent_t ev_c0 = nullptr, ev_c1 = nullptr;
    static bool init_done = false;
    const int GEMM_SMEM = (DIM * WS + 2 * TM * AS) * sizeof(uint32_t);  // 200KB
    if (!init_done) {
        cudaFuncSetAttribute(k_gemm, cudaFuncAttributeMaxDynamicSharedMemorySize, GEMM_SMEM);
        cudaStreamCreateWithFlags(&s2, cudaStreamNonBlocking);
        cudaEventCreateWithFlags(&ev_fork, cudaEventDisableTiming);
        cudaEventCreateWithFlags(&ev_join, cudaEventDisableTiming);
        cudaEventCreateWithFlags(&ev_g2, cudaEventDisableTiming);
        cudaEventCreateWithFlags(&ev_c0, cudaEventDisableTiming);
        cudaEventCreateWithFlags(&ev_c1, cudaEventDisableTiming);
        init_done = true;
    }
    const int GEMM_GRID = 148;

    __half* g_h_p;   cudaGetSymbolAddress((void**)&g_h_p, g_h);
    float*  g_z_p;   cudaGetSymbolAddress((void**)&g_z_p, g_z);
    __half* g_h2_p;  cudaGetSymbolAddress((void**)&g_h2_p, g_h2);

    // fork: CSR build (separate kernels — high-occupancy phases) on s2,
    // gemm1 on main (hidden behind CSR).
    cudaEventRecord(ev_fork, 0);
    cudaStreamWaitEvent(s2, ev_fork, 0);

    k_init<<<gN, T, 0, s2>>>(n);
    k_count<<<gE, T, 0, s2>>>(dst, ew, e);
    k_scan1<<<nScanBlk, SCAN_B, 0, s2>>>(n);
    k_gemm<<<GEMM_GRID, GEMM_T, GEMM_SMEM>>>(x, W1, g_h_p, n);
    k_scan3<<<nScanBlk, SCAN_B, 0, s2>>>(n);
    k_reorder<<<gE, T, 0, s2>>>(src, dst, ew, e);
    k_pad<<<gN, T, 0, s2>>>(n);
    cudaEventRecord(ev_join, s2);
    cudaStreamWaitEvent(0, ev_join, 0);

    // 2-chunk agg1 || gemm2 overlap. gemm2 writes g_h2.
    const int half = (n + 1) / 2;
    {
        int gWc = (half * 32 + T - 1) / T;
        k_agg<<<gWc, T>>>(g_h_p, b1, g_z_p, 0, half);
        cudaEventRecord(ev_c0, 0);
        cudaStreamWaitEvent(s2, ev_c0, 0);
        k_gemm<<<GEMM_GRID, GEMM_T, GEMM_SMEM, s2>>>(g_z_p, W2, g_h2_p, half);

        int nodes1 = n - half;
        int gWc1 = (nodes1 * 32 + T - 1) / T;
        k_agg<<<gWc1, T>>>(g_h_p, b1, g_z_p, half, n);
        cudaEventRecord(ev_c1, 0);
        cudaStreamWaitEvent(s2, ev_c1, 0);
        k_gemm<<<GEMM_GRID, GEMM_T, GEMM_SMEM, s2>>>(
            g_z_p + (size_t)half * DIM, W2, g_h2_p + (size_t)half * DIM, nodes1);
    }
    cudaEventRecord(ev_g2, s2);
    cudaStreamWaitEvent(0, ev_g2, 0);

    // layer 2 agg (full range), gathers from g_h2
    int gW = (n * 32 + T - 1) / T;
    k_agg<<<gW, T>>>(g_h2_p, b2, out, 0, n);
}